// round 8
// baseline (speedup 1.0000x reference)
#include <cuda_runtime.h>
#include <cstdint>

#define VOCAB 128
#define NTAGS 8
#define EDIM  256
#define HDIM  1024
#define BATCH 1024
#define SEQ   128

// ------------------------- device scratch (static, no allocs) -------------
__device__ float g_Q[VOCAB * HDIM];                       // 512 KB, L2-resident
__device__ int   g_len[BATCH];
__device__ float g_H[(size_t)SEQ * BATCH * HDIM];         // 512 MB: h after step t

// ===========================================================================
// Q[v][h] = sum_e emb[v][e] * W_ih[h][e] + b_ih[h] + b_hh[h]
// ===========================================================================
__global__ void q_kernel(const float* __restrict__ emb,
                         const float* __restrict__ W_ih,
                         const float* __restrict__ b_ih,
                         const float* __restrict__ b_hh) {
    int v = blockIdx.x;
    int warp = threadIdx.x >> 5, lane = threadIdx.x & 31;
    const float* e = emb + v * EDIM;
    for (int h = warp; h < HDIM; h += 8) {
        const float* w = W_ih + h * EDIM;
        float acc = 0.f;
        #pragma unroll
        for (int k = lane; k < EDIM; k += 32) acc += e[k] * w[k];
        #pragma unroll
        for (int o = 16; o > 0; o >>= 1) acc += __shfl_down_sync(0xffffffffu, acc, o);
        if (lane == 0) g_Q[v * HDIM + h] = acc + b_ih[h] + b_hh[h];
    }
}

// ===========================================================================
// seq_lengths + t=0 step (h0 = 0 so pre-activation is just Q[id0])
// ===========================================================================
__global__ void t0_kernel(const int* __restrict__ ids) {
    int b = blockIdx.x, tid = threadIdx.x;
    int m = (ids[b * SEQ + tid] != 0) ? 1 : 0;
    __shared__ int ws[4];
    #pragma unroll
    for (int o = 16; o > 0; o >>= 1) m += __shfl_down_sync(0xffffffffu, m, o);
    if ((tid & 31) == 0) ws[tid >> 5] = m;
    __syncthreads();
    int len = ws[0] + ws[1] + ws[2] + ws[3];
    if (tid == 0) g_len[b] = len;

    int id0 = ids[b * SEQ];
    const float* q = g_Q + (size_t)id0 * HDIM;
    float* hout = g_H + (size_t)b * HDIM;
    for (int h = tid; h < HDIM; h += 128)
        hout[h] = (len > 0) ? tanhf(q[h]) : 0.f;
}

// ===========================================================================
// step_kernel: tf32 m16n8k8, CTA tile 64x64, 128 threads (4 warps, warp
// tile 32x32). 3-stage cp.async pipeline, KCH=32, one barrier per chunk,
// register double-buffered fragments. grid = (16,16) = 256 CTAs,
// 2 CTAs/SM -> independent barriers interleave. PDL: prefetch W_hh stage 0
// before grid-dependency sync; trigger completion before the epilogue.
// ===========================================================================
#define KCH        32
#define NCH        (HDIM / KCH)            /* 32 */
#define SPITCH     36                      /* 36 ≡ 4 (mod 32): conflict-free */
#define A_FLOATS   (64 * SPITCH)           /* 2304 */
#define B_FLOATS   (64 * SPITCH)           /* 2304 */
#define STAGE_F    (A_FLOATS + B_FLOATS)   /* 4608 floats = 18432 B */
#define NSTAGE     3
#define STEP_SMEM  (NSTAGE * STAGE_F * 4)  /* 55296 B */

__device__ __forceinline__ void cp16(float* sp, const float* gp) {
    uint32_t s = (uint32_t)__cvta_generic_to_shared(sp);
    asm volatile("cp.async.cg.shared.global [%0], [%1], 16;\n" :: "r"(s), "l"(gp));
}

__device__ __forceinline__ void mma_tf32(float* d, const uint32_t* a, const uint32_t* b) {
    asm volatile(
        "mma.sync.aligned.m16n8k8.row.col.f32.tf32.tf32.f32 "
        "{%0,%1,%2,%3}, {%4,%5,%6,%7}, {%8,%9}, {%0,%1,%2,%3};\n"
        : "+f"(d[0]), "+f"(d[1]), "+f"(d[2]), "+f"(d[3])
        : "r"(a[0]), "r"(a[1]), "r"(a[2]), "r"(a[3]), "r"(b[0]), "r"(b[1]));
}

extern __shared__ float smem_dyn[];

__global__ void __launch_bounds__(128, 2)
step_kernel(const float* __restrict__ W_hh, const int* __restrict__ ids, int t) {
    const float* __restrict__ Hprev = g_H + (size_t)(t - 1) * BATCH * HDIM;
    float* __restrict__ Hout        = g_H + (size_t)t       * BATCH * HDIM;

    const int tid  = threadIdx.x;
    const int lane = tid & 31, warp = tid >> 5;
    const int wm = warp & 1, wn = warp >> 1;      // 2x2 warps, each 32x32
    const int g  = lane >> 2, c = lane & 3;
    const int m0 = blockIdx.y * 64;
    const int n0 = blockIdx.x * 64;

    float acc[2][4][4] = {};

    // ---- loaders: A = 64x32 (4 cp16/thr), B = 64x32 (4 cp16/thr) ----------
    #define LOAD_A(st, k0)                                                         \
        do {                                                                       \
            float* base = smem_dyn + (st) * STAGE_F;                               \
            _Pragma("unroll")                                                      \
            for (int i = 0; i < 4; i++) {                                          \
                int j = tid + i * 128;                                             \
                int r = j >> 3, c8 = j & 7;                                        \
                cp16(base + r * SPITCH + c8 * 4,                                   \
                     Hprev + (size_t)(m0 + r) * HDIM + (k0) + c8 * 4);             \
            }                                                                      \
        } while (0)
    #define LOAD_B(st, k0)                                                         \
        do {                                                                       \
            float* base = smem_dyn + (st) * STAGE_F + A_FLOATS;                    \
            _Pragma("unroll")                                                      \
            for (int i = 0; i < 4; i++) {                                          \
                int j = tid + i * 128;                                             \
                int r = j >> 3, c8 = j & 7;                                        \
                cp16(base + r * SPITCH + c8 * 4,                                   \
                     W_hh + (size_t)(n0 + r) * HDIM + (k0) + c8 * 4);              \
            }                                                                      \
        } while (0)

    #define LDFRAG(da, db, ksv)                                                    \
        do {                                                                       \
            _Pragma("unroll")                                                      \
            for (int mt = 0; mt < 2; mt++) {                                       \
                const float* ap = A + (mt * 16 + g) * SPITCH + (ksv) * 8 + c;      \
                da[mt][0] = __float_as_uint(ap[0]);                                \
                da[mt][1] = __float_as_uint(ap[8 * SPITCH]);                       \
                da[mt][2] = __float_as_uint(ap[4]);                                \
                da[mt][3] = __float_as_uint(ap[8 * SPITCH + 4]);                   \
            }                                                                      \
            _Pragma("unroll")                                                      \
            for (int nt = 0; nt < 4; nt++) {                                       \
                const float* bp = B + (nt * 8 + g) * SPITCH + (ksv) * 8 + c;       \
                db[nt][0] = __float_as_uint(bp[0]);                                \
                db[nt][1] = __float_as_uint(bp[4]);                                \
            }                                                                      \
        } while (0)

    // ---- PDL prologue: W_hh prefetch is step-invariant (safe pre-dep) -----
    LOAD_B(0, 0);
    asm volatile("cp.async.commit_group;\n");        // G0

    cudaGridDependencySynchronize();                 // wait: H[t-1] visible

    LOAD_A(0, 0);
    asm volatile("cp.async.commit_group;\n");        // G1
    LOAD_A(1, KCH); LOAD_B(1, KCH);
    asm volatile("cp.async.commit_group;\n");        // G2

    for (int ch = 0; ch < NCH; ch++) {
        if (ch < NCH - 1) asm volatile("cp.async.wait_group 1;\n");
        else              asm volatile("cp.async.wait_group 0;\n");
        __syncthreads();

        const int st = ch % NSTAGE;
        const float* A = smem_dyn + st * STAGE_F + (wm * 32) * SPITCH;
        const float* B = smem_dyn + st * STAGE_F + A_FLOATS + (wn * 32) * SPITCH;

        uint32_t af[2][2][4], bf[2][4][2];
        LDFRAG(af[0], bf[0], 0);
        #pragma unroll
        for (int ks = 0; ks < KCH / 8; ks++) {
            const int cur = ks & 1;
            if (ks < KCH / 8 - 1) LDFRAG(af[cur ^ 1], bf[cur ^ 1], ks + 1);
            #pragma unroll
            for (int mt = 0; mt < 2; mt++)
                #pragma unroll
                for (int nt = 0; nt < 4; nt++)
                    mma_tf32(acc[mt][nt], af[cur][mt], bf[cur][nt]);
        }
        // refill the stage freed at iteration ch-1 (barrier above protects it)
        if (ch + 2 < NCH) {
            const int st2 = (ch + 2) % NSTAGE;
            LOAD_A(st2, (ch + 2) * KCH);
            LOAD_B(st2, (ch + 2) * KCH);
            asm volatile("cp.async.commit_group;\n");
        }
    }

    // all Hprev tile loads done: let the next step start its W prefetch
    cudaTriggerProgrammaticLaunchCompletion();

    // ---- epilogue: + Q gather, tanh, mask ---------------------------------
    const int c2 = c * 2;
    #pragma unroll
    for (int mt = 0; mt < 2; mt++) {
        const int rA = m0 + wm * 32 + mt * 16 + g;
        const int rB = rA + 8;
        const int idA = ids[rA * SEQ + t];
        const int idB = ids[rB * SEQ + t];
        const bool mA = t < g_len[rA];
        const bool mB = t < g_len[rB];
        const float* q0 = g_Q + (size_t)idA * HDIM;
        const float* q1 = g_Q + (size_t)idB * HDIM;
        float* o0 = Hout + (size_t)rA * HDIM;
        float* o1 = Hout + (size_t)rB * HDIM;
        const float* p0 = Hprev + (size_t)rA * HDIM;
        const float* p1 = Hprev + (size_t)rB * HDIM;
        #pragma unroll
        for (int nt = 0; nt < 4; nt++) {
            const int n = n0 + wn * 32 + nt * 8 + c2;
            o0[n]     = mA ? tanhf(acc[mt][nt][0] + q0[n])     : p0[n];
            o0[n + 1] = mA ? tanhf(acc[mt][nt][1] + q0[n + 1]) : p0[n + 1];
            o1[n]     = mB ? tanhf(acc[mt][nt][2] + q1[n])     : p1[n];
            o1[n + 1] = mB ? tanhf(acc[mt][nt][3] + q1[n + 1]) : p1[n + 1];
        }
    }
    #undef LOAD_A
    #undef LOAD_B
    #undef LDFRAG
}

// ===========================================================================
// y[b][t][tag] = H[t][b][:] . W_out[tag][:] + b_out[tag]
// ===========================================================================
__global__ void y_kernel(const float* __restrict__ W_out,
                         const float* __restrict__ b_out,
                         float* __restrict__ y) {
    __shared__ float sW[NTAGS * HDIM];
    __shared__ float sb[NTAGS];
    for (int i = threadIdx.x; i < NTAGS * HDIM; i += 256) sW[i] = W_out[i];
    if (threadIdx.x < NTAGS) sb[threadIdx.x] = b_out[threadIdx.x];
    __syncthreads();

    const int r = blockIdx.x * 256 + threadIdx.x;   // r = b*SEQ + t
    const int b = r / SEQ, t = r % SEQ;
    const float4* h = (const float4*)(g_H + (size_t)t * BATCH * HDIM + (size_t)b * HDIM);

    float acc[NTAGS];
    #pragma unroll
    for (int tg = 0; tg < NTAGS; tg++) acc[tg] = sb[tg];

    #pragma unroll 4
    for (int k4 = 0; k4 < HDIM / 4; k4++) {
        const float4 hv = h[k4];
        #pragma unroll
        for (int tg = 0; tg < NTAGS; tg++) {
            const float4 wv = ((const float4*)(sW + tg * HDIM))[k4];
            acc[tg] += hv.x * wv.x + hv.y * wv.y + hv.z * wv.z + hv.w * wv.w;
        }
    }
    #pragma unroll
    for (int tg = 0; tg < NTAGS; tg++) y[(size_t)r * NTAGS + tg] = acc[tg];
}

// ===========================================================================
extern "C" void kernel_launch(void* const* d_in, const int* in_sizes, int n_in,
                              void* d_out, int out_size) {
    (void)in_sizes; (void)n_in; (void)out_size;
    const int*   ids   = (const int*)  d_in[0];
    const float* emb   = (const float*)d_in[1];
    const float* W_ih  = (const float*)d_in[2];
    const float* W_hh  = (const float*)d_in[3];
    const float* b_ih  = (const float*)d_in[4];
    const float* b_hh  = (const float*)d_in[5];
    const float* W_out = (const float*)d_in[6];
    const float* b_out = (const float*)d_in[7];
    float* y = (float*)d_out;

    cudaFuncSetAttribute(step_kernel,
                         cudaFuncAttributeMaxDynamicSharedMemorySize, STEP_SMEM);

    q_kernel<<<VOCAB, 256>>>(emb, W_ih, b_ih, b_hh);
    t0_kernel<<<BATCH, 128>>>(ids);

    cudaLaunchAttribute attrs[1];
    attrs[0].id = cudaLaunchAttributeProgrammaticStreamSerialization;
    attrs[0].val.programmaticStreamSerializationAllowed = 1;

    for (int t = 1; t < SEQ; t++) {
        cudaLaunchConfig_t cfg = {};
        cfg.gridDim = dim3(HDIM / 64, BATCH / 64);   // (16,16)=256 CTAs
        cfg.blockDim = dim3(128, 1, 1);
        cfg.dynamicSmemBytes = STEP_SMEM;
        cfg.stream = 0;
        cfg.attrs = attrs;
        cfg.numAttrs = 1;
        cudaLaunchKernelEx(&cfg, step_kernel, W_hh, ids, t);
    }

    y_kernel<<<(BATCH * SEQ) / 256, 256>>>(W_out, b_out, y);
}

// round 9
// speedup vs baseline: 1.0100x; 1.0100x over previous
#include <cuda_runtime.h>
#include <cstdint>

#define VOCAB 128
#define NTAGS 8
#define EDIM  256
#define HDIM  1024
#define BATCH 1024
#define SEQ   128

// ------------------------- device scratch (static, no allocs) -------------
__device__ float g_Q[VOCAB * HDIM];                       // 512 KB, L2-resident
__device__ int   g_len[BATCH];
__device__ float g_H[(size_t)SEQ * BATCH * HDIM];         // 512 MB: h after step t

// ===========================================================================
// Q[v][h] = sum_e emb[v][e] * W_ih[h][e] + b_ih[h] + b_hh[h]
// ===========================================================================
__global__ void q_kernel(const float* __restrict__ emb,
                         const float* __restrict__ W_ih,
                         const float* __restrict__ b_ih,
                         const float* __restrict__ b_hh) {
    int v = blockIdx.x;
    int warp = threadIdx.x >> 5, lane = threadIdx.x & 31;
    const float* e = emb + v * EDIM;
    for (int h = warp; h < HDIM; h += 8) {
        const float* w = W_ih + h * EDIM;
        float acc = 0.f;
        #pragma unroll
        for (int k = lane; k < EDIM; k += 32) acc += e[k] * w[k];
        #pragma unroll
        for (int o = 16; o > 0; o >>= 1) acc += __shfl_down_sync(0xffffffffu, acc, o);
        if (lane == 0) g_Q[v * HDIM + h] = acc + b_ih[h] + b_hh[h];
    }
}

// ===========================================================================
// seq_lengths + t=0 step (h0 = 0 so pre-activation is just Q[id0])
// ===========================================================================
__global__ void t0_kernel(const int* __restrict__ ids) {
    int b = blockIdx.x, tid = threadIdx.x;
    int m = (ids[b * SEQ + tid] != 0) ? 1 : 0;
    __shared__ int ws[4];
    #pragma unroll
    for (int o = 16; o > 0; o >>= 1) m += __shfl_down_sync(0xffffffffu, m, o);
    if ((tid & 31) == 0) ws[tid >> 5] = m;
    __syncthreads();
    int len = ws[0] + ws[1] + ws[2] + ws[3];
    if (tid == 0) g_len[b] = len;

    int id0 = ids[b * SEQ];
    const float* q = g_Q + (size_t)id0 * HDIM;
    float* hout = g_H + (size_t)b * HDIM;
    for (int h = tid; h < HDIM; h += 128)
        hout[h] = (len > 0) ? tanhf(q[h]) : 0.f;
}

// ===========================================================================
// step_kernel: tf32 m16n8k8, CTA tile 64x64, 128 threads (4 warps, warp
// tile 32x32). 3-stage cp.async pipeline, KCH=32, one barrier per chunk,
// register double-buffered fragments. grid = (16,16) = 256 CTAs,
// 2 CTAs/SM -> independent barriers interleave. PDL: prefetch W_hh stage 0
// before grid-dependency sync; trigger completion before the epilogue.
// ===========================================================================
#define KCH        32
#define NCH        (HDIM / KCH)            /* 32 */
#define SPITCH     36                      /* 36 ≡ 4 (mod 32): conflict-free */
#define A_FLOATS   (64 * SPITCH)           /* 2304 */
#define B_FLOATS   (64 * SPITCH)           /* 2304 */
#define STAGE_F    (A_FLOATS + B_FLOATS)   /* 4608 floats = 18432 B */
#define NSTAGE     3
#define STEP_SMEM  (NSTAGE * STAGE_F * 4)  /* 55296 B */

__device__ __forceinline__ void cp16(float* sp, const float* gp) {
    uint32_t s = (uint32_t)__cvta_generic_to_shared(sp);
    asm volatile("cp.async.cg.shared.global [%0], [%1], 16;\n" :: "r"(s), "l"(gp));
}

__device__ __forceinline__ void mma_tf32(float* d, const uint32_t* a, const uint32_t* b) {
    asm volatile(
        "mma.sync.aligned.m16n8k8.row.col.f32.tf32.tf32.f32 "
        "{%0,%1,%2,%3}, {%4,%5,%6,%7}, {%8,%9}, {%0,%1,%2,%3};\n"
        : "+f"(d[0]), "+f"(d[1]), "+f"(d[2]), "+f"(d[3])
        : "r"(a[0]), "r"(a[1]), "r"(a[2]), "r"(a[3]), "r"(b[0]), "r"(b[1]));
}

extern __shared__ float smem_dyn[];

__global__ void __launch_bounds__(128, 2)
step_kernel(const float* __restrict__ W_hh, const int* __restrict__ ids, int t) {
    const float* __restrict__ Hprev = g_H + (size_t)(t - 1) * BATCH * HDIM;
    float* __restrict__ Hout        = g_H + (size_t)t       * BATCH * HDIM;

    const int tid  = threadIdx.x;
    const int lane = tid & 31, warp = tid >> 5;
    const int wm = warp & 1, wn = warp >> 1;      // 2x2 warps, each 32x32
    const int g  = lane >> 2, c = lane & 3;
    const int m0 = blockIdx.y * 64;
    const int n0 = blockIdx.x * 64;

    float acc[2][4][4] = {};

    // ---- loaders: A = 64x32 (4 cp16/thr), B = 64x32 (4 cp16/thr) ----------
    #define LOAD_A(st, k0)                                                         \
        do {                                                                       \
            float* base = smem_dyn + (st) * STAGE_F;                               \
            _Pragma("unroll")                                                      \
            for (int i = 0; i < 4; i++) {                                          \
                int j = tid + i * 128;                                             \
                int r = j >> 3, c8 = j & 7;                                        \
                cp16(base + r * SPITCH + c8 * 4,                                   \
                     Hprev + (size_t)(m0 + r) * HDIM + (k0) + c8 * 4);             \
            }                                                                      \
        } while (0)
    #define LOAD_B(st, k0)                                                         \
        do {                                                                       \
            float* base = smem_dyn + (st) * STAGE_F + A_FLOATS;                    \
            _Pragma("unroll")                                                      \
            for (int i = 0; i < 4; i++) {                                          \
                int j = tid + i * 128;                                             \
                int r = j >> 3, c8 = j & 7;                                        \
                cp16(base + r * SPITCH + c8 * 4,                                   \
                     W_hh + (size_t)(n0 + r) * HDIM + (k0) + c8 * 4);              \
            }                                                                      \
        } while (0)

    #define LDFRAG(da, db, ksv)                                                    \
        do {                                                                       \
            _Pragma("unroll")                                                      \
            for (int mt = 0; mt < 2; mt++) {                                       \
                const float* ap = A + (mt * 16 + g) * SPITCH + (ksv) * 8 + c;      \
                da[mt][0] = __float_as_uint(ap[0]);                                \
                da[mt][1] = __float_as_uint(ap[8 * SPITCH]);                       \
                da[mt][2] = __float_as_uint(ap[4]);                                \
                da[mt][3] = __float_as_uint(ap[8 * SPITCH + 4]);                   \
            }                                                                      \
            _Pragma("unroll")                                                      \
            for (int nt = 0; nt < 4; nt++) {                                       \
                const float* bp = B + (nt * 8 + g) * SPITCH + (ksv) * 8 + c;       \
                db[nt][0] = __float_as_uint(bp[0]);                                \
                db[nt][1] = __float_as_uint(bp[4]);                                \
            }                                                                      \
        } while (0)

    // ---- PDL prologue: W_hh prefetch is step-invariant (safe pre-dep) -----
    LOAD_B(0, 0);
    asm volatile("cp.async.commit_group;\n");        // G0

    cudaGridDependencySynchronize();                 // wait: H[t-1] visible

    LOAD_A(0, 0);
    asm volatile("cp.async.commit_group;\n");        // G1
    LOAD_A(1, KCH); LOAD_B(1, KCH);
    asm volatile("cp.async.commit_group;\n");        // G2

    for (int ch = 0; ch < NCH; ch++) {
        if (ch < NCH - 1) asm volatile("cp.async.wait_group 1;\n");
        else              asm volatile("cp.async.wait_group 0;\n");
        __syncthreads();

        const int st = ch % NSTAGE;
        const float* A = smem_dyn + st * STAGE_F + (wm * 32) * SPITCH;
        const float* B = smem_dyn + st * STAGE_F + A_FLOATS + (wn * 32) * SPITCH;

        uint32_t af[2][2][4], bf[2][4][2];
        LDFRAG(af[0], bf[0], 0);
        #pragma unroll
        for (int ks = 0; ks < KCH / 8; ks++) {
            const int cur = ks & 1;
            if (ks < KCH / 8 - 1) LDFRAG(af[cur ^ 1], bf[cur ^ 1], ks + 1);
            #pragma unroll
            for (int mt = 0; mt < 2; mt++)
                #pragma unroll
                for (int nt = 0; nt < 4; nt++)
                    mma_tf32(acc[mt][nt], af[cur][mt], bf[cur][nt]);
        }
        // refill the stage freed at iteration ch-1 (barrier above protects it)
        if (ch + 2 < NCH) {
            const int st2 = (ch + 2) % NSTAGE;
            LOAD_A(st2, (ch + 2) * KCH);
            LOAD_B(st2, (ch + 2) * KCH);
            asm volatile("cp.async.commit_group;\n");
        }
    }

    // all Hprev tile loads done: let the next step start its W prefetch
    cudaTriggerProgrammaticLaunchCompletion();

    // ---- epilogue: + Q gather, tanh, mask ---------------------------------
    const int c2 = c * 2;
    #pragma unroll
    for (int mt = 0; mt < 2; mt++) {
        const int rA = m0 + wm * 32 + mt * 16 + g;
        const int rB = rA + 8;
        const int idA = ids[rA * SEQ + t];
        const int idB = ids[rB * SEQ + t];
        const bool mA = t < g_len[rA];
        const bool mB = t < g_len[rB];
        const float* q0 = g_Q + (size_t)idA * HDIM;
        const float* q1 = g_Q + (size_t)idB * HDIM;
        float* o0 = Hout + (size_t)rA * HDIM;
        float* o1 = Hout + (size_t)rB * HDIM;
        const float* p0 = Hprev + (size_t)rA * HDIM;
        const float* p1 = Hprev + (size_t)rB * HDIM;
        #pragma unroll
        for (int nt = 0; nt < 4; nt++) {
            const int n = n0 + wn * 32 + nt * 8 + c2;
            o0[n]     = mA ? tanhf(acc[mt][nt][0] + q0[n])     : p0[n];
            o0[n + 1] = mA ? tanhf(acc[mt][nt][1] + q0[n + 1]) : p0[n + 1];
            o1[n]     = mB ? tanhf(acc[mt][nt][2] + q1[n])     : p1[n];
            o1[n + 1] = mB ? tanhf(acc[mt][nt][3] + q1[n + 1]) : p1[n + 1];
        }
    }
    #undef LOAD_A
    #undef LOAD_B
    #undef LDFRAG
}

// ===========================================================================
// y[b][t][tag] = H[t][b][:] . W_out[tag][:] + b_out[tag]
// ===========================================================================
__global__ void y_kernel(const float* __restrict__ W_out,
                         const float* __restrict__ b_out,
                         float* __restrict__ y) {
    __shared__ float sW[NTAGS * HDIM];
    __shared__ float sb[NTAGS];
    for (int i = threadIdx.x; i < NTAGS * HDIM; i += 256) sW[i] = W_out[i];
    if (threadIdx.x < NTAGS) sb[threadIdx.x] = b_out[threadIdx.x];
    __syncthreads();

    const int r = blockIdx.x * 256 + threadIdx.x;   // r = b*SEQ + t
    const int b = r / SEQ, t = r % SEQ;
    const float4* h = (const float4*)(g_H + (size_t)t * BATCH * HDIM + (size_t)b * HDIM);

    float acc[NTAGS];
    #pragma unroll
    for (int tg = 0; tg < NTAGS; tg++) acc[tg] = sb[tg];

    #pragma unroll 4
    for (int k4 = 0; k4 < HDIM / 4; k4++) {
        const float4 hv = h[k4];
        #pragma unroll
        for (int tg = 0; tg < NTAGS; tg++) {
            const float4 wv = ((const float4*)(sW + tg * HDIM))[k4];
            acc[tg] += hv.x * wv.x + hv.y * wv.y + hv.z * wv.z + hv.w * wv.w;
        }
    }
    #pragma unroll
    for (int tg = 0; tg < NTAGS; tg++) y[(size_t)r * NTAGS + tg] = acc[tg];
}

// ===========================================================================
extern "C" void kernel_launch(void* const* d_in, const int* in_sizes, int n_in,
                              void* d_out, int out_size) {
    (void)in_sizes; (void)n_in; (void)out_size;
    const int*   ids   = (const int*)  d_in[0];
    const float* emb   = (const float*)d_in[1];
    const float* W_ih  = (const float*)d_in[2];
    const float* W_hh  = (const float*)d_in[3];
    const float* b_ih  = (const float*)d_in[4];
    const float* b_hh  = (const float*)d_in[5];
    const float* W_out = (const float*)d_in[6];
    const float* b_out = (const float*)d_in[7];
    float* y = (float*)d_out;

    cudaFuncSetAttribute(step_kernel,
                         cudaFuncAttributeMaxDynamicSharedMemorySize, STEP_SMEM);

    q_kernel<<<VOCAB, 256>>>(emb, W_ih, b_ih, b_hh);
    t0_kernel<<<BATCH, 128>>>(ids);

    cudaLaunchAttribute attrs[1];
    attrs[0].id = cudaLaunchAttributeProgrammaticStreamSerialization;
    attrs[0].val.programmaticStreamSerializationAllowed = 1;

    for (int t = 1; t < SEQ; t++) {
        cudaLaunchConfig_t cfg = {};
        cfg.gridDim = dim3(HDIM / 64, BATCH / 64);   // (16,16)=256 CTAs
        cfg.blockDim = dim3(128, 1, 1);
        cfg.dynamicSmemBytes = STEP_SMEM;
        cfg.stream = 0;
        cfg.attrs = attrs;
        cfg.numAttrs = 1;
        cudaLaunchKernelEx(&cfg, step_kernel, W_hh, ids, t);
    }

    y_kernel<<<(BATCH * SEQ) / 256, 256>>>(W_out, b_out, y);
}

// round 10
// speedup vs baseline: 1.2981x; 1.2853x over previous
#include <cuda_runtime.h>
#include <cstdint>

#define VOCAB 128
#define NTAGS 8
#define EDIM  256
#define HDIM  1024
#define BATCH 1024
#define SEQ   128

// ------------------------- device scratch (static, no allocs) -------------
__device__ float    g_Q[VOCAB * HDIM];                    // 512 KB, L2-resident
__device__ int      g_len[BATCH];
__device__ float    g_H[(size_t)SEQ * BATCH * HDIM];      // 512 MB: h after step t
__device__ unsigned g_bar[8];                             // per-group step counters

// ===========================================================================
// Q[v][h] = sum_e emb[v][e] * W_ih[h][e] + b_ih[h] + b_hh[h]
// ===========================================================================
__global__ void q_kernel(const float* __restrict__ emb,
                         const float* __restrict__ W_ih,
                         const float* __restrict__ b_ih,
                         const float* __restrict__ b_hh) {
    int v = blockIdx.x;
    int warp = threadIdx.x >> 5, lane = threadIdx.x & 31;
    const float* e = emb + v * EDIM;
    for (int h = warp; h < HDIM; h += 8) {
        const float* w = W_ih + h * EDIM;
        float acc = 0.f;
        #pragma unroll
        for (int k = lane; k < EDIM; k += 32) acc += e[k] * w[k];
        #pragma unroll
        for (int o = 16; o > 0; o >>= 1) acc += __shfl_down_sync(0xffffffffu, acc, o);
        if (lane == 0) g_Q[v * HDIM + h] = acc + b_ih[h] + b_hh[h];
    }
}

// ===========================================================================
// seq_lengths + t=0 step (h0 = 0) + reset group barriers
// ===========================================================================
__global__ void t0_kernel(const int* __restrict__ ids) {
    int b = blockIdx.x, tid = threadIdx.x;
    if (b < 8 && tid == 0) g_bar[b] = 0u;   // reset persistent-kernel barriers

    int m = (ids[b * SEQ + tid] != 0) ? 1 : 0;
    __shared__ int ws[4];
    #pragma unroll
    for (int o = 16; o > 0; o >>= 1) m += __shfl_down_sync(0xffffffffu, m, o);
    if ((tid & 31) == 0) ws[tid >> 5] = m;
    __syncthreads();
    int len = ws[0] + ws[1] + ws[2] + ws[3];
    if (tid == 0) g_len[b] = len;

    int id0 = ids[b * SEQ];
    const float* q = g_Q + (size_t)id0 * HDIM;
    float* hout = g_H + (size_t)b * HDIM;
    for (int h = tid; h < HDIM; h += 128)
        hout[h] = (len > 0) ? tanhf(q[h]) : 0.f;
}

// ===========================================================================
// rnn_kernel: PERSISTENT — one launch runs all 127 steps.
// 128 CTAs (1/SM, all resident), 256 threads, CTA tile 128x64.
// Group g = CTAs [16g,16g+16) owns batch rows [128g,128g+128); per-step
// sync is a 16-CTA atomic arrive/spin barrier (groups drift independently).
// GEMM: tf32 m16n8k8, warp tile 32x32 (4x2 warps), KCH=64, 16 chunks,
// 3-stage cp.async pipeline (lookahead 2), register double-buffered frags.
// W_hh stage-0/1 tiles for step t+1 prefetched before the barrier spin.
// ===========================================================================
#define KCH        64
#define NCHK       (HDIM / KCH)            /* 16 */
#define PITCH      68                      /* 68 ≡ 4 (mod 32): conflict-free */
#define A_F        (128 * PITCH)           /* 8704 floats */
#define B_F        (64  * PITCH)           /* 4352 floats */
#define STAGE_F    (A_F + B_F)             /* 13056 floats = 52224 B */
#define NST        3
#define RNN_SMEM   (NST * STAGE_F * 4)     /* 156672 B */

__device__ __forceinline__ void cp16(float* sp, const float* gp) {
    uint32_t s = (uint32_t)__cvta_generic_to_shared(sp);
    asm volatile("cp.async.cg.shared.global [%0], [%1], 16;\n" :: "r"(s), "l"(gp));
}

__device__ __forceinline__ void mma_tf32(float* d, const uint32_t* a, const uint32_t* b) {
    asm volatile(
        "mma.sync.aligned.m16n8k8.row.col.f32.tf32.tf32.f32 "
        "{%0,%1,%2,%3}, {%4,%5,%6,%7}, {%8,%9}, {%0,%1,%2,%3};\n"
        : "+f"(d[0]), "+f"(d[1]), "+f"(d[2]), "+f"(d[3])
        : "r"(a[0]), "r"(a[1]), "r"(a[2]), "r"(a[3]), "r"(b[0]), "r"(b[1]));
}

extern __shared__ float smem_dyn[];

__global__ void __launch_bounds__(256, 1)
rnn_kernel(const float* __restrict__ W_hh, const int* __restrict__ ids) {
    const int tid  = threadIdx.x;
    const int lane = tid & 31, warp = tid >> 5;
    const int wm = warp & 3, wn = warp >> 2;       // 4x2 warps, each 32x32
    const int g  = lane >> 2, c = lane & 3;
    const int grp = blockIdx.x >> 4;
    const int sub = blockIdx.x & 15;
    const int m0 = grp * 128;
    const int n0 = sub * 64;
    volatile unsigned* bar = &g_bar[grp];

    // ---- loaders -----------------------------------------------------------
    // A: 128 rows x 64 cols = 2048 float4 -> 8 cp16/thread
    #define LOAD_A(st, k0, Hp)                                                     \
        do {                                                                       \
            float* base = smem_dyn + (st) * STAGE_F;                               \
            _Pragma("unroll")                                                      \
            for (int i = 0; i < 8; i++) {                                          \
                int j = tid + i * 256;                                             \
                int r = j >> 4, c16 = j & 15;                                      \
                cp16(base + r * PITCH + c16 * 4,                                   \
                     (Hp) + (size_t)(m0 + r) * HDIM + (k0) + c16 * 4);             \
            }                                                                      \
        } while (0)
    // B: 64 rows x 64 cols = 1024 float4 -> 4 cp16/thread
    #define LOAD_B(st, k0)                                                         \
        do {                                                                       \
            float* base = smem_dyn + (st) * STAGE_F + A_F;                         \
            _Pragma("unroll")                                                      \
            for (int i = 0; i < 4; i++) {                                          \
                int j = tid + i * 256;                                             \
                int r = j >> 4, c16 = j & 15;                                      \
                cp16(base + r * PITCH + c16 * 4,                                   \
                     W_hh + (size_t)(n0 + r) * HDIM + (k0) + c16 * 4);             \
            }                                                                      \
        } while (0)

    #define LDFRAG(da, db, ksv)                                                    \
        do {                                                                       \
            _Pragma("unroll")                                                      \
            for (int mt = 0; mt < 2; mt++) {                                       \
                const float* ap = A + (mt * 16 + g) * PITCH + (ksv) * 8 + c;       \
                da[mt][0] = __float_as_uint(ap[0]);                                \
                da[mt][1] = __float_as_uint(ap[8 * PITCH]);                        \
                da[mt][2] = __float_as_uint(ap[4]);                                \
                da[mt][3] = __float_as_uint(ap[8 * PITCH + 4]);                    \
            }                                                                      \
            _Pragma("unroll")                                                      \
            for (int nt = 0; nt < 4; nt++) {                                       \
                const float* bp = B + (nt * 8 + g) * PITCH + (ksv) * 8 + c;        \
                db[nt][0] = __float_as_uint(bp[0]);                                \
                db[nt][1] = __float_as_uint(bp[4]);                                \
            }                                                                      \
        } while (0)

    // W stage 0/1 prefetch for the first step (uncommitted; joins group 0)
    LOAD_B(0, 0);
    LOAD_B(1, KCH);

    for (int t = 1; t < SEQ; t++) {
        const float* __restrict__ Hprev = g_H + (size_t)(t - 1) * BATCH * HDIM;
        float* __restrict__ Hout        = g_H + (size_t)t       * BATCH * HDIM;

        float acc[2][4][4] = {};

        LOAD_A(0, 0, Hprev);
        asm volatile("cp.async.commit_group;\n");   // {B0, B1, A0}
        LOAD_A(1, KCH, Hprev);
        asm volatile("cp.async.commit_group;\n");   // {A1}

        for (int ch = 0; ch < NCHK; ch++) {
            if (ch < NCHK - 1) asm volatile("cp.async.wait_group 1;\n");
            else               asm volatile("cp.async.wait_group 0;\n");
            __syncthreads();

            const int st = ch % NST;
            const float* A = smem_dyn + st * STAGE_F + (wm * 32) * PITCH;
            const float* B = smem_dyn + st * STAGE_F + A_F + (wn * 32) * PITCH;

            uint32_t af[2][2][4], bf[2][4][2];
            LDFRAG(af[0], bf[0], 0);
            #pragma unroll
            for (int ks = 0; ks < KCH / 8; ks++) {
                const int cur = ks & 1;
                if (ks < KCH / 8 - 1) LDFRAG(af[cur ^ 1], bf[cur ^ 1], ks + 1);
                #pragma unroll
                for (int mt = 0; mt < 2; mt++)
                    #pragma unroll
                    for (int nt = 0; nt < 4; nt++)
                        mma_tf32(acc[mt][nt], af[cur][mt], bf[cur][nt]);
            }
            if (ch + 2 < NCHK) {
                const int st2 = (ch + 2) % NST;
                LOAD_A(st2, (ch + 2) * KCH, Hprev);
                LOAD_B(st2, (ch + 2) * KCH);
                asm volatile("cp.async.commit_group;\n");
            }
        }

        // all warps done with stage 0/1 before overwriting their B halves
        __syncthreads();
        if (t + 1 < SEQ) {        // W prefetch for next step (step-invariant)
            LOAD_B(0, 0);
            LOAD_B(1, KCH);
        }

        // ---- epilogue: + Q gather, tanh, mask ------------------------------
        const int c2 = c * 2;
        #pragma unroll
        for (int mt = 0; mt < 2; mt++) {
            const int rA = m0 + wm * 32 + mt * 16 + g;
            const int rB = rA + 8;
            const int idA = ids[rA * SEQ + t];
            const int idB = ids[rB * SEQ + t];
            const bool mA = t < g_len[rA];
            const bool mB = t < g_len[rB];
            const float* q0 = g_Q + (size_t)idA * HDIM;
            const float* q1 = g_Q + (size_t)idB * HDIM;
            float* o0 = Hout + (size_t)rA * HDIM;
            float* o1 = Hout + (size_t)rB * HDIM;
            const float* p0 = Hprev + (size_t)rA * HDIM;
            const float* p1 = Hprev + (size_t)rB * HDIM;
            #pragma unroll
            for (int nt = 0; nt < 4; nt++) {
                const int n = n0 + wn * 32 + nt * 8 + c2;
                o0[n]     = mA ? tanhf(acc[mt][nt][0] + q0[n])     : p0[n];
                o0[n + 1] = mA ? tanhf(acc[mt][nt][1] + q0[n + 1]) : p0[n + 1];
                o1[n]     = mB ? tanhf(acc[mt][nt][2] + q1[n])     : p1[n];
                o1[n + 1] = mB ? tanhf(acc[mt][nt][3] + q1[n + 1]) : p1[n + 1];
            }
        }

        if (t + 1 >= SEQ) break;                  // last step: no barrier needed

        // ---- group barrier: release own H[t] slice, acquire the others -----
        __threadfence();                          // publish this thread's stores
        __syncthreads();                          // all threads fenced
        if (tid == 0) {
            atomicAdd((unsigned*)&g_bar[grp], 1u);
            unsigned target = 16u * (unsigned)t;
            while (*bar < target) __nanosleep(32);
        }
        __syncthreads();
        __threadfence();                          // acquire before reading H[t]
    }
    #undef LOAD_A
    #undef LOAD_B
    #undef LDFRAG
}

// ===========================================================================
// y[b][t][tag] = H[t][b][:] . W_out[tag][:] + b_out[tag]
// ===========================================================================
__global__ void y_kernel(const float* __restrict__ W_out,
                         const float* __restrict__ b_out,
                         float* __restrict__ y) {
    __shared__ float sW[NTAGS * HDIM];
    __shared__ float sb[NTAGS];
    for (int i = threadIdx.x; i < NTAGS * HDIM; i += 256) sW[i] = W_out[i];
    if (threadIdx.x < NTAGS) sb[threadIdx.x] = b_out[threadIdx.x];
    __syncthreads();

    const int r = blockIdx.x * 256 + threadIdx.x;   // r = b*SEQ + t
    const int b = r / SEQ, t = r % SEQ;
    const float4* h = (const float4*)(g_H + (size_t)t * BATCH * HDIM + (size_t)b * HDIM);

    float acc[NTAGS];
    #pragma unroll
    for (int tg = 0; tg < NTAGS; tg++) acc[tg] = sb[tg];

    #pragma unroll 4
    for (int k4 = 0; k4 < HDIM / 4; k4++) {
        const float4 hv = h[k4];
        #pragma unroll
        for (int tg = 0; tg < NTAGS; tg++) {
            const float4 wv = ((const float4*)(sW + tg * HDIM))[k4];
            acc[tg] += hv.x * wv.x + hv.y * wv.y + hv.z * wv.z + hv.w * wv.w;
        }
    }
    #pragma unroll
    for (int tg = 0; tg < NTAGS; tg++) y[(size_t)r * NTAGS + tg] = acc[tg];
}

// ===========================================================================
extern "C" void kernel_launch(void* const* d_in, const int* in_sizes, int n_in,
                              void* d_out, int out_size) {
    (void)in_sizes; (void)n_in; (void)out_size;
    const int*   ids   = (const int*)  d_in[0];
    const float* emb   = (const float*)d_in[1];
    const float* W_ih  = (const float*)d_in[2];
    const float* W_hh  = (const float*)d_in[3];
    const float* b_ih  = (const float*)d_in[4];
    const float* b_hh  = (const float*)d_in[5];
    const float* W_out = (const float*)d_in[6];
    const float* b_out = (const float*)d_in[7];
    float* y = (float*)d_out;

    cudaFuncSetAttribute(rnn_kernel,
                         cudaFuncAttributeMaxDynamicSharedMemorySize, RNN_SMEM);

    q_kernel<<<VOCAB, 256>>>(emb, W_ih, b_ih, b_hh);
    t0_kernel<<<BATCH, 128>>>(ids);
    rnn_kernel<<<128, 256, RNN_SMEM>>>(W_hh, ids);   // persistent: all 127 steps
    y_kernel<<<(BATCH * SEQ) / 256, 256>>>(W_out, b_out, y);
}